// round 7
// baseline (speedup 1.0000x reference)
#include <cuda_runtime.h>
#include <cuda_bf16.h>
#include <cstdint>

// MaxUnpooling2D scatter-add.
//   updates: f32 [8,128,128,256] = 33,554,432 elems (134 MB)
//   mask:    i32 same shape, values in [0, 2^24)
//   out:     f32 [8,256,256,256] = 134,217,728 elems (536 MB)
//   flat index = mask[i] + batch * 2^22  (batch offset uses INPUT size)
// Touched output range: [0, 2^24 + 7*2^22) = [0, 46,137,344) words.
//
// R6 structure (atomics are SM-side wavefront-bound, ~invariant to L2 policy):
//   1. zero touched range (ordering hazard with atomics)
//   2. ONE fused kernel: scatter blocks + tail-zero blocks run concurrently —
//      tail zero is DRAM-write bound, scatter is LSU/L1tex-wavefront bound.

static constexpr int N_UPD   = 33554432;    // update elems (8 * 2^22)
static constexpr int N_OUT   = 134217728;   // output elems (8 * 2^24)
static constexpr int TOUCHED = 46137344;    // 2^24 + 7*2^22
static constexpr int BATCH_SHIFT = 22;

static constexpr int SCATTER_BLOCKS = (N_UPD / 4) / 256;          // 32768
static constexpr int TAIL_BLOCKS    = ((N_OUT - TOUCHED) / 4) / 256; // 86016

// Zero the touched range (dirty lines may stay in L2; harmless either way).
__global__ void __launch_bounds__(256) zero_touched_kernel(float4* __restrict__ out) {
    int i = blockIdx.x * 256 + threadIdx.x;
    out[i] = make_float4(0.f, 0.f, 0.f, 0.f);
}

// Fused: blocks [0, SCATTER_BLOCKS) scatter; the rest zero the tail.
__global__ void __launch_bounds__(256) scatter_and_tail_kernel(
    const float4* __restrict__ upd4,
    const int4*  __restrict__ mask4,
    float* __restrict__ out)
{
    int bid = blockIdx.x;
    if (bid < SCATTER_BLOCKS) {
        int i = bid * 256 + threadIdx.x;           // float4 index
        int4   m = __ldcs(mask4 + i);
        float4 u = __ldcs(upd4 + i);
        // elem index = 4*i -> batch = i >> 20; base = batch << 22
        int base = (i >> (BATCH_SHIFT - 2)) << BATCH_SHIFT;
        atomicAdd(out + (base + m.x), u.x);
        atomicAdd(out + (base + m.y), u.y);
        atomicAdd(out + (base + m.z), u.z);
        atomicAdd(out + (base + m.w), u.w);
    } else {
        // Tail zero: [TOUCHED, N_OUT), streaming stores (never re-read).
        int j = (bid - SCATTER_BLOCKS) * 256 + threadIdx.x;
        __stcs((float4*)out + (TOUCHED / 4) + j,
               make_float4(0.f, 0.f, 0.f, 0.f));
    }
}

extern "C" void kernel_launch(void* const* d_in, const int* in_sizes, int n_in,
                              void* d_out, int out_size) {
    const float* updates = (const float*)d_in[0];
    const int*   mask    = (const int*)d_in[1];
    float* out = (float*)d_out;

    // 1. Zero the touched range [0, TOUCHED) — must precede all atomics.
    zero_touched_kernel<<<(TOUCHED / 4) / 256, 256>>>((float4*)out);

    // 2. Fused scatter + tail zero.
    scatter_and_tail_kernel<<<SCATTER_BLOCKS + TAIL_BLOCKS, 256>>>(
        (const float4*)updates, (const int4*)mask, out);
}